// round 1
// baseline (speedup 1.0000x reference)
#include <cuda_runtime.h>
#include <cstddef>

#define Nb 64
#define Ts 512
#define Dd 1024
#define Hh 1024
#define Gg 4096   // 4*Hh

typedef unsigned long long u64;

// Scratch: xW in (t, n, 4H) layout. 512 MB static device array (allowed; no allocs).
__device__ float g_xw[(size_t)Nb * Ts * Gg];
__device__ float g_hbuf[2][Nb * Hh];
__device__ float g_cbuf[Nb * Hh];

union F2U { u64 u; float2 f; };
union F4U { float4 f; u64 u[2]; };

#define FFMA2(d, a, b) asm("fma.rn.f32x2 %0, %1, %2, %0;" : "+l"(d) : "l"(a), "l"(b))
#define PACK2(d, s)    asm("mov.b64 %0, {%1, %1};" : "=l"(d) : "r"(s))

__device__ __forceinline__ void cp16(void* smem, const void* g) {
    unsigned saddr = (unsigned)__cvta_generic_to_shared(smem);
    asm volatile("cp.async.cg.shared.global [%0], [%1], 16;" :: "r"(saddr), "l"(g));
}
#define CP_COMMIT() asm volatile("cp.async.commit_group;")
#define CP_WAIT1()  asm volatile("cp.async.wait_group 1;")

// ===================================================================
// Kernel 1: xW[t*64+n][g] = bias[g] + sum_d x[n][t][d] * Wx[d][g]
// M=32768, N=4096, K=1024.  BM=128 BN=128 BK=16, 256 thr, 8x8/thread (f32x2).
// ===================================================================
__global__ __launch_bounds__(256) void xw_gemm(const float* __restrict__ x,
                                               const float* __restrict__ Wx,
                                               const float* __restrict__ bias) {
    __shared__ float As[2][128][20];   // [row][k], padded row=20 floats (16B-aligned chunks)
    __shared__ float Bs[2][16][128];   // [k][g]

    const int tid  = threadIdx.x;
    const int row0 = blockIdx.y * 128;
    const int col0 = blockIdx.x * 128;
    const int tx = tid & 15, ty = tid >> 4;

    // load maps
    const int arow = tid >> 2;          // 0..63 (and +64)
    const int ak   = (tid & 3) << 2;    // 0,4,8,12
    const int brow = tid >> 5;          // 0..7 (and +8)
    const int bcol = (tid & 31) << 2;   // 0..124

    F2U acc[8][4];
    #pragma unroll
    for (int i = 0; i < 8; i++)
        #pragma unroll
        for (int j = 0; j < 4; j++) acc[i][j].u = 0ull;

    // prefetch tile kt=0 into buf 0
    {
        #pragma unroll
        for (int rr = 0; rr < 2; rr++) {
            int r = arow + rr * 64;
            int m = row0 + r;
            int t = m >> 6, n = m & 63;
            cp16(&As[0][r][ak], x + ((size_t)n * Ts + t) * Dd + 0 + ak);
        }
        #pragma unroll
        for (int rr = 0; rr < 2; rr++) {
            int rb = brow + rr * 8;
            cp16(&Bs[0][rb][bcol], Wx + (size_t)(0 + rb) * Gg + col0 + bcol);
        }
        CP_COMMIT();
    }

    int buf = 0;
    for (int kt = 0; kt < Dd; kt += 16) {
        // prefetch next tile into other buffer
        if (kt + 16 < Dd) {
            #pragma unroll
            for (int rr = 0; rr < 2; rr++) {
                int r = arow + rr * 64;
                int m = row0 + r;
                int t = m >> 6, n = m & 63;
                cp16(&As[buf ^ 1][r][ak], x + ((size_t)n * Ts + t) * Dd + (kt + 16) + ak);
            }
            #pragma unroll
            for (int rr = 0; rr < 2; rr++) {
                int rb = brow + rr * 8;
                cp16(&Bs[buf ^ 1][rb][bcol], Wx + (size_t)(kt + 16 + rb) * Gg + col0 + bcol);
            }
        }
        CP_COMMIT();
        CP_WAIT1();
        __syncthreads();

        const float (*Asb)[20]  = As[buf];
        const float (*Bsb)[128] = Bs[buf];
        #pragma unroll
        for (int k = 0; k < 16; k++) {
            float a[8];
            #pragma unroll
            for (int i = 0; i < 8; i++) a[i] = Asb[ty * 8 + i][k];
            const u64* bp = (const u64*)&Bsb[k][tx * 8];
            u64 b2[4];
            b2[0] = bp[0]; b2[1] = bp[1]; b2[2] = bp[2]; b2[3] = bp[3];
            #pragma unroll
            for (int i = 0; i < 8; i++) {
                u64 a2; PACK2(a2, __float_as_uint(a[i]));
                FFMA2(acc[i][0].u, a2, b2[0]);
                FFMA2(acc[i][1].u, a2, b2[1]);
                FFMA2(acc[i][2].u, a2, b2[2]);
                FFMA2(acc[i][3].u, a2, b2[3]);
            }
        }
        __syncthreads();
        buf ^= 1;
    }

    // epilogue: add bias, store
    #pragma unroll
    for (int i = 0; i < 8; i++) {
        size_t m = (size_t)(row0 + ty * 8 + i);
        float* outp = g_xw + m * Gg + col0 + tx * 8;
        #pragma unroll
        for (int j = 0; j < 4; j++) {
            float2 v = acc[i][j].f;
            v.x += bias[col0 + tx * 8 + 2 * j + 0];
            v.y += bias[col0 + tx * 8 + 2 * j + 1];
            *(float2*)(outp + 2 * j) = v;
        }
    }
}

// ===================================================================
// Kernel 2: one LSTM step.
// Block jb owns hidden cols j0..j0+7 (all 4 gates, all 64 rows).
// A[n][gate*8+jj] = xw[t][n][gate*H + j0+jj] + sum_k h[n][k]*Wh[k][gate*H + j0+jj]
// 256 threads, each a 2x4 register tile (2 rows x 2 f32x2 col-pairs), K tiled by 32.
// ===================================================================
__global__ __launch_bounds__(256) void lstm_step(const float* __restrict__ Wh,
                                                 const float* __restrict__ h0,
                                                 float* __restrict__ out,
                                                 int t) {
    __shared__ float h_s[2][64][36];
    __shared__ float W_s[2][32][36];
    __shared__ float A_s[64][33];

    const int tid = threadIdx.x;
    const int j0  = blockIdx.x * 8;

    const float* h_in  = (t == 0) ? h0 : g_hbuf[t & 1];
    float*       h_out = g_hbuf[(t + 1) & 1];
    const float* xw    = g_xw + (size_t)t * Nb * Gg;

    // compute map: thread -> rows {n0, n0+1}, cols {c0..c0+3} of the 32 block cols
    const int cg = tid & 7;        const int c0 = cg * 4;
    const int rg = tid >> 3;       const int n0 = rg * 2;

    // load maps
    const int hn = tid >> 2;            // 0..63
    const int hk = (tid & 3) << 3;      // 0,8,16,24 (two 16B chunks each)
    const int wk = tid >> 3;            // 0..31
    const int wc = (tid & 7) << 2;      // 0,4,...,28
    const int wgate = wc >> 3;
    const int wjj   = wc & 7;
    const float* wgptr = Wh + (size_t)wgate * Hh + j0 + wjj;   // + (kt+wk)*Gg per tile

    F2U acc[2][2];
    acc[0][0].u = 0ull; acc[0][1].u = 0ull; acc[1][0].u = 0ull; acc[1][1].u = 0ull;

    // prefetch kt=0
    {
        cp16(&h_s[0][hn][hk + 0], h_in + hn * Hh + 0 + hk + 0);
        cp16(&h_s[0][hn][hk + 4], h_in + hn * Hh + 0 + hk + 4);
        cp16(&W_s[0][wk][wc],     wgptr + (size_t)(0 + wk) * Gg);
        CP_COMMIT();
    }

    int buf = 0;
    for (int kt = 0; kt < Hh; kt += 32) {
        if (kt + 32 < Hh) {
            cp16(&h_s[buf ^ 1][hn][hk + 0], h_in + hn * Hh + (kt + 32) + hk + 0);
            cp16(&h_s[buf ^ 1][hn][hk + 4], h_in + hn * Hh + (kt + 32) + hk + 4);
            cp16(&W_s[buf ^ 1][wk][wc],     wgptr + (size_t)(kt + 32 + wk) * Gg);
        }
        CP_COMMIT();
        CP_WAIT1();
        __syncthreads();

        const float (*hsb)[36] = h_s[buf];
        const float (*wsb)[36] = W_s[buf];
        #pragma unroll
        for (int kk = 0; kk < 32; kk += 2) {
            float2 aA = *(const float2*)&hsb[n0][kk];
            float2 aB = *(const float2*)&hsb[n0 + 1][kk];
            F4U w0, w1;
            w0.f = *(const float4*)&wsb[kk][c0];
            w1.f = *(const float4*)&wsb[kk + 1][c0];
            u64 d0, d1;
            PACK2(d0, __float_as_uint(aA.x));
            PACK2(d1, __float_as_uint(aB.x));
            FFMA2(acc[0][0].u, d0, w0.u[0]); FFMA2(acc[0][1].u, d0, w0.u[1]);
            FFMA2(acc[1][0].u, d1, w0.u[0]); FFMA2(acc[1][1].u, d1, w0.u[1]);
            PACK2(d0, __float_as_uint(aA.y));
            PACK2(d1, __float_as_uint(aB.y));
            FFMA2(acc[0][0].u, d0, w1.u[0]); FFMA2(acc[0][1].u, d0, w1.u[1]);
            FFMA2(acc[1][0].u, d1, w1.u[0]); FFMA2(acc[1][1].u, d1, w1.u[1]);
        }
        __syncthreads();
        buf ^= 1;
    }

    // stage A tile to smem so gates line up per (n, jj)
    #pragma unroll
    for (int r = 0; r < 2; r++) {
        #pragma unroll
        for (int p = 0; p < 2; p++) {
            A_s[n0 + r][c0 + 2 * p + 0] = acc[r][p].f.x;
            A_s[n0 + r][c0 + 2 * p + 1] = acc[r][p].f.y;
        }
    }
    __syncthreads();

    // elementwise gates: 512 (n,jj) pairs, 2 per thread
    #pragma unroll
    for (int q = 0; q < 2; q++) {
        int p  = q * 256 + tid;
        int n  = p >> 3;
        int jj = p & 7;
        size_t xb = (size_t)n * Gg + j0 + jj;
        float ai = A_s[n][0  + jj] + xw[xb + 0 * Hh];
        float af = A_s[n][8  + jj] + xw[xb + 1 * Hh];
        float ao = A_s[n][16 + jj] + xw[xb + 2 * Hh];
        float ag = A_s[n][24 + jj] + xw[xb + 3 * Hh];

        float ig = 1.0f / (1.0f + __expf(-ai));
        float fg = 1.0f / (1.0f + __expf(-af));
        float og = 1.0f / (1.0f + __expf(-ao));
        float gg = tanhf(ag);

        int ci = n * Hh + j0 + jj;
        float cprev = (t == 0) ? 0.0f : g_cbuf[ci];
        float cn = fg * cprev + ig * gg;
        g_cbuf[ci] = cn;
        float hv = og * tanhf(cn);
        h_out[ci] = hv;
        out[((size_t)n * Ts + t) * Hh + j0 + jj] = hv;
    }
}

extern "C" void kernel_launch(void* const* d_in, const int* in_sizes, int n_in,
                              void* d_out, int out_size) {
    const float* x  = (const float*)d_in[0];   // (64, 512, 1024)
    const float* h0 = (const float*)d_in[1];   // (64, 1024)
    const float* Wx = (const float*)d_in[2];   // (1024, 4096)
    const float* Wh = (const float*)d_in[3];   // (1024, 4096)
    const float* b  = (const float*)d_in[4];   // (4096)
    float* out = (float*)d_out;                // (64, 512, 1024)

    dim3 g1(Gg / 128, (Nb * Ts) / 128);        // (32, 256)
    xw_gemm<<<g1, 256>>>(x, Wx, b);

    for (int t = 0; t < Ts; t++) {
        lstm_step<<<Hh / 8, 256>>>(Wh, h0, out, t);
    }
}

// round 2
// speedup vs baseline: 1.0005x; 1.0005x over previous
#include <cuda_runtime.h>
#include <cstddef>

#define Nb 64
#define Ts 512
#define Dd 1024
#define Hh 1024
#define Gg 4096   // 4*Hh

typedef unsigned long long u64;

// Scratch: xW in (t, n, 4H) layout. 512 MB static device array (allowed; no allocs).
__device__ float g_xw[(size_t)Nb * Ts * Gg];
__device__ float g_hbuf[2][Nb * Hh];
__device__ float g_cbuf[Nb * Hh];

union F2U { u64 u; float2 f; };
union F4U { float4 f; u64 u[2]; };

#define FFMA2(d, a, b) asm("fma.rn.f32x2 %0, %1, %2, %0;" : "+l"(d) : "l"(a), "l"(b))
#define PACK2(d, s)    asm("mov.b64 %0, {%1, %1};" : "=l"(d) : "r"(s))

__device__ __forceinline__ void cp16(void* smem, const void* g) {
    unsigned saddr = (unsigned)__cvta_generic_to_shared(smem);
    asm volatile("cp.async.cg.shared.global [%0], [%1], 16;" :: "r"(saddr), "l"(g));
}
#define CP_COMMIT() asm volatile("cp.async.commit_group;")
#define CP_WAIT1()  asm volatile("cp.async.wait_group 1;")

// ===================================================================
// Kernel 1: xW[t*64+n][g] = bias[g] + sum_d x[n][t][d] * Wx[d][g]
// M=32768, N=4096, K=1024.  BM=128 BN=128 BK=16, 256 thr, 8x8/thread (f32x2).
// ===================================================================
__global__ __launch_bounds__(256) void xw_gemm(const float* __restrict__ x,
                                               const float* __restrict__ Wx,
                                               const float* __restrict__ bias) {
    __shared__ float As[2][128][20];   // [row][k], padded row=20 floats (16B-aligned chunks)
    __shared__ float Bs[2][16][128];   // [k][g]

    const int tid  = threadIdx.x;
    const int row0 = blockIdx.y * 128;
    const int col0 = blockIdx.x * 128;
    const int tx = tid & 15, ty = tid >> 4;

    // load maps
    const int arow = tid >> 2;          // 0..63 (and +64)
    const int ak   = (tid & 3) << 2;    // 0,4,8,12
    const int brow = tid >> 5;          // 0..7 (and +8)
    const int bcol = (tid & 31) << 2;   // 0..124

    F2U acc[8][4];
    #pragma unroll
    for (int i = 0; i < 8; i++)
        #pragma unroll
        for (int j = 0; j < 4; j++) acc[i][j].u = 0ull;

    // prefetch tile kt=0 into buf 0
    {
        #pragma unroll
        for (int rr = 0; rr < 2; rr++) {
            int r = arow + rr * 64;
            int m = row0 + r;
            int t = m >> 6, n = m & 63;
            cp16(&As[0][r][ak], x + ((size_t)n * Ts + t) * Dd + 0 + ak);
        }
        #pragma unroll
        for (int rr = 0; rr < 2; rr++) {
            int rb = brow + rr * 8;
            cp16(&Bs[0][rb][bcol], Wx + (size_t)(0 + rb) * Gg + col0 + bcol);
        }
        CP_COMMIT();
    }

    int buf = 0;
    for (int kt = 0; kt < Dd; kt += 16) {
        // prefetch next tile into other buffer
        if (kt + 16 < Dd) {
            #pragma unroll
            for (int rr = 0; rr < 2; rr++) {
                int r = arow + rr * 64;
                int m = row0 + r;
                int t = m >> 6, n = m & 63;
                cp16(&As[buf ^ 1][r][ak], x + ((size_t)n * Ts + t) * Dd + (kt + 16) + ak);
            }
            #pragma unroll
            for (int rr = 0; rr < 2; rr++) {
                int rb = brow + rr * 8;
                cp16(&Bs[buf ^ 1][rb][bcol], Wx + (size_t)(kt + 16 + rb) * Gg + col0 + bcol);
            }
        }
        CP_COMMIT();
        CP_WAIT1();
        __syncthreads();

        const float (*Asb)[20]  = As[buf];
        const float (*Bsb)[128] = Bs[buf];
        #pragma unroll
        for (int k = 0; k < 16; k++) {
            float a[8];
            #pragma unroll
            for (int i = 0; i < 8; i++) a[i] = Asb[ty * 8 + i][k];
            const u64* bp = (const u64*)&Bsb[k][tx * 8];
            u64 b2[4];
            b2[0] = bp[0]; b2[1] = bp[1]; b2[2] = bp[2]; b2[3] = bp[3];
            #pragma unroll
            for (int i = 0; i < 8; i++) {
                u64 a2; PACK2(a2, __float_as_uint(a[i]));
                FFMA2(acc[i][0].u, a2, b2[0]);
                FFMA2(acc[i][1].u, a2, b2[1]);
                FFMA2(acc[i][2].u, a2, b2[2]);
                FFMA2(acc[i][3].u, a2, b2[3]);
            }
        }
        __syncthreads();
        buf ^= 1;
    }

    // epilogue: add bias, store
    #pragma unroll
    for (int i = 0; i < 8; i++) {
        size_t m = (size_t)(row0 + ty * 8 + i);
        float* outp = g_xw + m * Gg + col0 + tx * 8;
        #pragma unroll
        for (int j = 0; j < 4; j++) {
            float2 v = acc[i][j].f;
            v.x += bias[col0 + tx * 8 + 2 * j + 0];
            v.y += bias[col0 + tx * 8 + 2 * j + 1];
            *(float2*)(outp + 2 * j) = v;
        }
    }
}

// ===================================================================
// Kernel 2: one LSTM step.
// Block jb owns hidden cols j0..j0+7 (all 4 gates, all 64 rows).
// A[n][gate*8+jj] = xw[t][n][gate*H + j0+jj] + sum_k h[n][k]*Wh[k][gate*H + j0+jj]
// 256 threads, each a 2x4 register tile (2 rows x 2 f32x2 col-pairs), K tiled by 32.
// ===================================================================
__global__ __launch_bounds__(256) void lstm_step(const float* __restrict__ Wh,
                                                 const float* __restrict__ h0,
                                                 float* __restrict__ out,
                                                 int t) {
    __shared__ float h_s[2][64][36];
    __shared__ float W_s[2][32][36];
    __shared__ float A_s[64][33];

    const int tid = threadIdx.x;
    const int j0  = blockIdx.x * 8;

    const float* h_in  = (t == 0) ? h0 : g_hbuf[t & 1];
    float*       h_out = g_hbuf[(t + 1) & 1];
    const float* xw    = g_xw + (size_t)t * Nb * Gg;

    // compute map: thread -> rows {n0, n0+1}, cols {c0..c0+3} of the 32 block cols
    const int cg = tid & 7;        const int c0 = cg * 4;
    const int rg = tid >> 3;       const int n0 = rg * 2;

    // load maps
    const int hn = tid >> 2;            // 0..63
    const int hk = (tid & 3) << 3;      // 0,8,16,24 (two 16B chunks each)
    const int wk = tid >> 3;            // 0..31
    const int wc = (tid & 7) << 2;      // 0,4,...,28
    const int wgate = wc >> 3;
    const int wjj   = wc & 7;
    const float* wgptr = Wh + (size_t)wgate * Hh + j0 + wjj;   // + (kt+wk)*Gg per tile

    F2U acc[2][2];
    acc[0][0].u = 0ull; acc[0][1].u = 0ull; acc[1][0].u = 0ull; acc[1][1].u = 0ull;

    // prefetch kt=0
    {
        cp16(&h_s[0][hn][hk + 0], h_in + hn * Hh + 0 + hk + 0);
        cp16(&h_s[0][hn][hk + 4], h_in + hn * Hh + 0 + hk + 4);
        cp16(&W_s[0][wk][wc],     wgptr + (size_t)(0 + wk) * Gg);
        CP_COMMIT();
    }

    int buf = 0;
    for (int kt = 0; kt < Hh; kt += 32) {
        if (kt + 32 < Hh) {
            cp16(&h_s[buf ^ 1][hn][hk + 0], h_in + hn * Hh + (kt + 32) + hk + 0);
            cp16(&h_s[buf ^ 1][hn][hk + 4], h_in + hn * Hh + (kt + 32) + hk + 4);
            cp16(&W_s[buf ^ 1][wk][wc],     wgptr + (size_t)(kt + 32 + wk) * Gg);
        }
        CP_COMMIT();
        CP_WAIT1();
        __syncthreads();

        const float (*hsb)[36] = h_s[buf];
        const float (*wsb)[36] = W_s[buf];
        #pragma unroll
        for (int kk = 0; kk < 32; kk += 2) {
            float2 aA = *(const float2*)&hsb[n0][kk];
            float2 aB = *(const float2*)&hsb[n0 + 1][kk];
            F4U w0, w1;
            w0.f = *(const float4*)&wsb[kk][c0];
            w1.f = *(const float4*)&wsb[kk + 1][c0];
            u64 d0, d1;
            PACK2(d0, __float_as_uint(aA.x));
            PACK2(d1, __float_as_uint(aB.x));
            FFMA2(acc[0][0].u, d0, w0.u[0]); FFMA2(acc[0][1].u, d0, w0.u[1]);
            FFMA2(acc[1][0].u, d1, w0.u[0]); FFMA2(acc[1][1].u, d1, w0.u[1]);
            PACK2(d0, __float_as_uint(aA.y));
            PACK2(d1, __float_as_uint(aB.y));
            FFMA2(acc[0][0].u, d0, w1.u[0]); FFMA2(acc[0][1].u, d0, w1.u[1]);
            FFMA2(acc[1][0].u, d1, w1.u[0]); FFMA2(acc[1][1].u, d1, w1.u[1]);
        }
        __syncthreads();
        buf ^= 1;
    }

    // stage A tile to smem so gates line up per (n, jj)
    #pragma unroll
    for (int r = 0; r < 2; r++) {
        #pragma unroll
        for (int p = 0; p < 2; p++) {
            A_s[n0 + r][c0 + 2 * p + 0] = acc[r][p].f.x;
            A_s[n0 + r][c0 + 2 * p + 1] = acc[r][p].f.y;
        }
    }
    __syncthreads();

    // elementwise gates: 512 (n,jj) pairs, 2 per thread
    #pragma unroll
    for (int q = 0; q < 2; q++) {
        int p  = q * 256 + tid;
        int n  = p >> 3;
        int jj = p & 7;
        size_t xb = (size_t)n * Gg + j0 + jj;
        float ai = A_s[n][0  + jj] + xw[xb + 0 * Hh];
        float af = A_s[n][8  + jj] + xw[xb + 1 * Hh];
        float ao = A_s[n][16 + jj] + xw[xb + 2 * Hh];
        float ag = A_s[n][24 + jj] + xw[xb + 3 * Hh];

        float ig = 1.0f / (1.0f + __expf(-ai));
        float fg = 1.0f / (1.0f + __expf(-af));
        float og = 1.0f / (1.0f + __expf(-ao));
        float gg = tanhf(ag);

        int ci = n * Hh + j0 + jj;
        float cprev = (t == 0) ? 0.0f : g_cbuf[ci];
        float cn = fg * cprev + ig * gg;
        g_cbuf[ci] = cn;
        float hv = og * tanhf(cn);
        h_out[ci] = hv;
        out[((size_t)n * Ts + t) * Hh + j0 + jj] = hv;
    }
}

extern "C" void kernel_launch(void* const* d_in, const int* in_sizes, int n_in,
                              void* d_out, int out_size) {
    const float* x  = (const float*)d_in[0];   // (64, 512, 1024)
    const float* h0 = (const float*)d_in[1];   // (64, 1024)
    const float* Wx = (const float*)d_in[2];   // (1024, 4096)
    const float* Wh = (const float*)d_in[3];   // (1024, 4096)
    const float* b  = (const float*)d_in[4];   // (4096)
    float* out = (float*)d_out;                // (64, 512, 1024)

    dim3 g1(Gg / 128, (Nb * Ts) / 128);        // (32, 256)
    xw_gemm<<<g1, 256>>>(x, Wx, b);

    for (int t = 0; t < Ts; t++) {
        lstm_step<<<Hh / 8, 256>>>(Wh, h0, out, t);
    }
}

// round 3
// speedup vs baseline: 1.0021x; 1.0016x over previous
#include <cuda_runtime.h>
#include <cstddef>

#define Nb 64
#define Ts 512
#define Dd 1024
#define Hh 1024
#define Gg 4096   // 4*Hh

typedef unsigned long long u64;

// Scratch: xW in (t, n, 4H) layout. 512 MB static device array (allowed; no allocs).
__device__ float g_xw[(size_t)Nb * Ts * Gg];
__device__ float g_hbuf[2][Nb * Hh];
__device__ float g_cbuf[Nb * Hh];

union F2U { u64 u; float2 f; };
union F4U { float4 f; u64 u[2]; };

#define FFMA2(d, a, b) asm("fma.rn.f32x2 %0, %1, %2, %0;" : "+l"(d) : "l"(a), "l"(b))
#define PACK2(d, s)    asm("mov.b64 %0, {%1, %1};" : "=l"(d) : "r"(s))

__device__ __forceinline__ void cp16(void* smem, const void* g) {
    unsigned saddr = (unsigned)__cvta_generic_to_shared(smem);
    asm volatile("cp.async.cg.shared.global [%0], [%1], 16;" :: "r"(saddr), "l"(g));
}
#define CP_COMMIT() asm volatile("cp.async.commit_group;")
#define CP_WAIT1()  asm volatile("cp.async.wait_group 1;")

// ===================================================================
// Kernel 1: xW[t*64+n][g] = bias[g] + sum_d x[n][t][d] * Wx[d][g]
// M=32768, N=4096, K=1024.  BM=128 BN=128 BK=16, 256 thr, 8x8/thread (f32x2).
// ===================================================================
__global__ __launch_bounds__(256) void xw_gemm(const float* __restrict__ x,
                                               const float* __restrict__ Wx,
                                               const float* __restrict__ bias) {
    __shared__ float As[2][128][20];   // [row][k], padded row=20 floats (16B-aligned chunks)
    __shared__ float Bs[2][16][128];   // [k][g]

    const int tid  = threadIdx.x;
    const int row0 = blockIdx.y * 128;
    const int col0 = blockIdx.x * 128;
    const int tx = tid & 15, ty = tid >> 4;

    // load maps
    const int arow = tid >> 2;          // 0..63 (and +64)
    const int ak   = (tid & 3) << 2;    // 0,4,8,12
    const int brow = tid >> 5;          // 0..7 (and +8)
    const int bcol = (tid & 31) << 2;   // 0..124

    F2U acc[8][4];
    #pragma unroll
    for (int i = 0; i < 8; i++)
        #pragma unroll
        for (int j = 0; j < 4; j++) acc[i][j].u = 0ull;

    // prefetch tile kt=0 into buf 0
    {
        #pragma unroll
        for (int rr = 0; rr < 2; rr++) {
            int r = arow + rr * 64;
            int m = row0 + r;
            int t = m >> 6, n = m & 63;
            cp16(&As[0][r][ak], x + ((size_t)n * Ts + t) * Dd + 0 + ak);
        }
        #pragma unroll
        for (int rr = 0; rr < 2; rr++) {
            int rb = brow + rr * 8;
            cp16(&Bs[0][rb][bcol], Wx + (size_t)(0 + rb) * Gg + col0 + bcol);
        }
        CP_COMMIT();
    }

    int buf = 0;
    for (int kt = 0; kt < Dd; kt += 16) {
        // prefetch next tile into other buffer
        if (kt + 16 < Dd) {
            #pragma unroll
            for (int rr = 0; rr < 2; rr++) {
                int r = arow + rr * 64;
                int m = row0 + r;
                int t = m >> 6, n = m & 63;
                cp16(&As[buf ^ 1][r][ak], x + ((size_t)n * Ts + t) * Dd + (kt + 16) + ak);
            }
            #pragma unroll
            for (int rr = 0; rr < 2; rr++) {
                int rb = brow + rr * 8;
                cp16(&Bs[buf ^ 1][rb][bcol], Wx + (size_t)(kt + 16 + rb) * Gg + col0 + bcol);
            }
        }
        CP_COMMIT();
        CP_WAIT1();
        __syncthreads();

        const float (*Asb)[20]  = As[buf];
        const float (*Bsb)[128] = Bs[buf];
        #pragma unroll
        for (int k = 0; k < 16; k++) {
            float a[8];
            #pragma unroll
            for (int i = 0; i < 8; i++) a[i] = Asb[ty * 8 + i][k];
            const u64* bp = (const u64*)&Bsb[k][tx * 8];
            u64 b2[4];
            b2[0] = bp[0]; b2[1] = bp[1]; b2[2] = bp[2]; b2[3] = bp[3];
            #pragma unroll
            for (int i = 0; i < 8; i++) {
                u64 a2; PACK2(a2, __float_as_uint(a[i]));
                FFMA2(acc[i][0].u, a2, b2[0]);
                FFMA2(acc[i][1].u, a2, b2[1]);
                FFMA2(acc[i][2].u, a2, b2[2]);
                FFMA2(acc[i][3].u, a2, b2[3]);
            }
        }
        __syncthreads();
        buf ^= 1;
    }

    // epilogue: add bias, store
    #pragma unroll
    for (int i = 0; i < 8; i++) {
        size_t m = (size_t)(row0 + ty * 8 + i);
        float* outp = g_xw + m * Gg + col0 + tx * 8;
        #pragma unroll
        for (int j = 0; j < 4; j++) {
            float2 v = acc[i][j].f;
            v.x += bias[col0 + tx * 8 + 2 * j + 0];
            v.y += bias[col0 + tx * 8 + 2 * j + 1];
            *(float2*)(outp + 2 * j) = v;
        }
    }
}

// ===================================================================
// Kernel 2: one LSTM step.
// Block jb owns hidden cols j0..j0+7 (all 4 gates, all 64 rows).
// A[n][gate*8+jj] = xw[t][n][gate*H + j0+jj] + sum_k h[n][k]*Wh[k][gate*H + j0+jj]
// 256 threads, each a 2x4 register tile (2 rows x 2 f32x2 col-pairs), K tiled by 32.
// ===================================================================
__global__ __launch_bounds__(256) void lstm_step(const float* __restrict__ Wh,
                                                 const float* __restrict__ h0,
                                                 float* __restrict__ out,
                                                 int t) {
    __shared__ float h_s[2][64][36];
    __shared__ float W_s[2][32][36];
    __shared__ float A_s[64][33];

    const int tid = threadIdx.x;
    const int j0  = blockIdx.x * 8;

    const float* h_in  = (t == 0) ? h0 : g_hbuf[t & 1];
    float*       h_out = g_hbuf[(t + 1) & 1];
    const float* xw    = g_xw + (size_t)t * Nb * Gg;

    // compute map: thread -> rows {n0, n0+1}, cols {c0..c0+3} of the 32 block cols
    const int cg = tid & 7;        const int c0 = cg * 4;
    const int rg = tid >> 3;       const int n0 = rg * 2;

    // load maps
    const int hn = tid >> 2;            // 0..63
    const int hk = (tid & 3) << 3;      // 0,8,16,24 (two 16B chunks each)
    const int wk = tid >> 3;            // 0..31
    const int wc = (tid & 7) << 2;      // 0,4,...,28
    const int wgate = wc >> 3;
    const int wjj   = wc & 7;
    const float* wgptr = Wh + (size_t)wgate * Hh + j0 + wjj;   // + (kt+wk)*Gg per tile

    F2U acc[2][2];
    acc[0][0].u = 0ull; acc[0][1].u = 0ull; acc[1][0].u = 0ull; acc[1][1].u = 0ull;

    // prefetch kt=0
    {
        cp16(&h_s[0][hn][hk + 0], h_in + hn * Hh + 0 + hk + 0);
        cp16(&h_s[0][hn][hk + 4], h_in + hn * Hh + 0 + hk + 4);
        cp16(&W_s[0][wk][wc],     wgptr + (size_t)(0 + wk) * Gg);
        CP_COMMIT();
    }

    int buf = 0;
    for (int kt = 0; kt < Hh; kt += 32) {
        if (kt + 32 < Hh) {
            cp16(&h_s[buf ^ 1][hn][hk + 0], h_in + hn * Hh + (kt + 32) + hk + 0);
            cp16(&h_s[buf ^ 1][hn][hk + 4], h_in + hn * Hh + (kt + 32) + hk + 4);
            cp16(&W_s[buf ^ 1][wk][wc],     wgptr + (size_t)(kt + 32 + wk) * Gg);
        }
        CP_COMMIT();
        CP_WAIT1();
        __syncthreads();

        const float (*hsb)[36] = h_s[buf];
        const float (*wsb)[36] = W_s[buf];
        #pragma unroll
        for (int kk = 0; kk < 32; kk += 2) {
            float2 aA = *(const float2*)&hsb[n0][kk];
            float2 aB = *(const float2*)&hsb[n0 + 1][kk];
            F4U w0, w1;
            w0.f = *(const float4*)&wsb[kk][c0];
            w1.f = *(const float4*)&wsb[kk + 1][c0];
            u64 d0, d1;
            PACK2(d0, __float_as_uint(aA.x));
            PACK2(d1, __float_as_uint(aB.x));
            FFMA2(acc[0][0].u, d0, w0.u[0]); FFMA2(acc[0][1].u, d0, w0.u[1]);
            FFMA2(acc[1][0].u, d1, w0.u[0]); FFMA2(acc[1][1].u, d1, w0.u[1]);
            PACK2(d0, __float_as_uint(aA.y));
            PACK2(d1, __float_as_uint(aB.y));
            FFMA2(acc[0][0].u, d0, w1.u[0]); FFMA2(acc[0][1].u, d0, w1.u[1]);
            FFMA2(acc[1][0].u, d1, w1.u[0]); FFMA2(acc[1][1].u, d1, w1.u[1]);
        }
        __syncthreads();
        buf ^= 1;
    }

    // stage A tile to smem so gates line up per (n, jj)
    #pragma unroll
    for (int r = 0; r < 2; r++) {
        #pragma unroll
        for (int p = 0; p < 2; p++) {
            A_s[n0 + r][c0 + 2 * p + 0] = acc[r][p].f.x;
            A_s[n0 + r][c0 + 2 * p + 1] = acc[r][p].f.y;
        }
    }
    __syncthreads();

    // elementwise gates: 512 (n,jj) pairs, 2 per thread
    #pragma unroll
    for (int q = 0; q < 2; q++) {
        int p  = q * 256 + tid;
        int n  = p >> 3;
        int jj = p & 7;
        size_t xb = (size_t)n * Gg + j0 + jj;
        float ai = A_s[n][0  + jj] + xw[xb + 0 * Hh];
        float af = A_s[n][8  + jj] + xw[xb + 1 * Hh];
        float ao = A_s[n][16 + jj] + xw[xb + 2 * Hh];
        float ag = A_s[n][24 + jj] + xw[xb + 3 * Hh];

        float ig = 1.0f / (1.0f + __expf(-ai));
        float fg = 1.0f / (1.0f + __expf(-af));
        float og = 1.0f / (1.0f + __expf(-ao));
        float gg = tanhf(ag);

        int ci = n * Hh + j0 + jj;
        float cprev = (t == 0) ? 0.0f : g_cbuf[ci];
        float cn = fg * cprev + ig * gg;
        g_cbuf[ci] = cn;
        float hv = og * tanhf(cn);
        h_out[ci] = hv;
        out[((size_t)n * Ts + t) * Hh + j0 + jj] = hv;
    }
}

extern "C" void kernel_launch(void* const* d_in, const int* in_sizes, int n_in,
                              void* d_out, int out_size) {
    const float* x  = (const float*)d_in[0];   // (64, 512, 1024)
    const float* h0 = (const float*)d_in[1];   // (64, 1024)
    const float* Wx = (const float*)d_in[2];   // (1024, 4096)
    const float* Wh = (const float*)d_in[3];   // (1024, 4096)
    const float* b  = (const float*)d_in[4];   // (4096)
    float* out = (float*)d_out;                // (64, 512, 1024)

    dim3 g1(Gg / 128, (Nb * Ts) / 128);        // (32, 256)
    xw_gemm<<<g1, 256>>>(x, Wx, b);

    for (int t = 0; t < Ts; t++) {
        lstm_step<<<Hh / 8, 256>>>(Wh, h0, out, t);
    }
}